// round 16
// baseline (speedup 1.0000x reference)
#include <cuda_runtime.h>
#include <cuda_fp16.h>
#include <cstdint>
#include <math.h>

#define V 33
#define V3 (V*V*V)          // 35937
#define BATCH 2
#define HW 2048
#define NPIX (HW*HW)

// ---------------- scratch (static device globals; no allocation) -------------
__device__ float  g_rs[BATCH*3*256*256];
__device__ float  g_a1[BATCH*16*128*128];
__device__ float  g_a2[BATCH*32*64*64];
__device__ float  g_a3[BATCH*64*32*32];
__device__ float  g_a4[BATCH*128*16*16];
__device__ float  g_a5[BATCH*128*8*8];
__device__ float  g_wts[BATCH*3];
// abs-kink bin table: per (b,c,k): {m0, m1, d1, qstar}; s(q)=m0+m1*q+d1*|q-qstar|
__device__ float4 g_tbl[BATCH*3*256];
// full-cell 64B entries: all 8 corners x 3ch (48B payload), 1 L1 line/pixel
__device__ uint4 g_lut8[BATCH*V3*4];

__device__ __forceinline__ unsigned int h2u(__half2 h) {
    return *reinterpret_cast<unsigned int*>(&h);
}

// ---------------- stage 1: bilinear 2048 -> 256 (scale exactly 8) ------------
__global__ void resize_k(const float* __restrict__ img) {
    int i = blockIdx.x * blockDim.x + threadIdx.x;
    if (i >= BATCH*3*256*256) return;
    int ox = i & 255;
    int oy = (i >> 8) & 255;
    int pc = i >> 16;                       // b*3 + c
    const float* p = img + (size_t)pc * NPIX;
    int iy = oy*8 + 3, ix = ox*8 + 3;
    float p00 = p[(size_t)iy*HW + ix];
    float p01 = p[(size_t)iy*HW + ix + 1];
    float p10 = p[(size_t)(iy+1)*HW + ix];
    float p11 = p[(size_t)(iy+1)*HW + ix + 1];
    float r0 = 0.5f*p00 + 0.5f*p10;
    float r1 = 0.5f*p01 + 0.5f*p11;
    g_rs[i] = 0.5f*r0 + 0.5f*r1;
}

// ------- thread-per-output conv, weights in smem (shallow CI) ----------------
template<int CI, int CO, int HIN, int TPB>
__global__ __launch_bounds__(TPB) void conv_k(const float* __restrict__ in,
                       const float* __restrict__ w,
                       const float* __restrict__ bias, float* __restrict__ out) {
    const int HO = HIN / 2;
    const int PLANE = HO * HO;
    const int BPP = PLANE / TPB;
    int blk  = blockIdx.x;
    int pix  = (blk % BPP) * TPB + threadIdx.x;
    int co   = (blk / BPP) % CO;
    int b    = blk / (BPP * CO);

    __shared__ float sw[CI*9];
    for (int i = threadIdx.x; i < CI*9; i += TPB) sw[i] = w[(size_t)co*CI*9 + i];
    __syncthreads();

    int ox = pix % HO;
    int oy = pix / HO;
    float acc = bias[co];
    const float* ib = in + (size_t)b*CI*HIN*HIN;
    int iy0 = oy*2 - 1, ix0 = ox*2 - 1;
    if (iy0 >= 0 && ix0 >= 0) {
        const float* ip = ib + (size_t)iy0*HIN + ix0;
        const float* wp = sw;
        for (int ci = 0; ci < CI; ci++) {
            acc += ip[0]      *wp[0] + ip[1]      *wp[1] + ip[2]      *wp[2];
            acc += ip[HIN]    *wp[3] + ip[HIN+1]  *wp[4] + ip[HIN+2]  *wp[5];
            acc += ip[2*HIN]  *wp[6] + ip[2*HIN+1]*wp[7] + ip[2*HIN+2]*wp[8];
            ip += HIN*HIN;
            wp += 9;
        }
    } else {
        for (int ci = 0; ci < CI; ci++) {
            const float* ip = ib + (size_t)ci*HIN*HIN;
            const float* wp = sw + ci*9;
            #pragma unroll
            for (int ky = 0; ky < 3; ky++) {
                int iy = iy0 + ky;
                if ((unsigned)iy >= (unsigned)HIN) continue;
                #pragma unroll
                for (int kx = 0; kx < 3; kx++) {
                    int ix = ix0 + kx;
                    if ((unsigned)ix >= (unsigned)HIN) continue;
                    acc += ip[iy*HIN + ix] * wp[ky*3 + kx];
                }
            }
        }
    }
    out[(size_t)(b*CO + co)*PLANE + pix] = acc >= 0.f ? acc : 0.2f*acc;
}

// ---- ci-split conv: block = PT pixels x S ci-groups; smem tree-reduce -------
template<int CI, int CO, int HIN, int PT, int S, int TPB>
__global__ __launch_bounds__(TPB) void convs_k(const float* __restrict__ in,
                       const float* __restrict__ w,
                       const float* __restrict__ bias, float* __restrict__ out) {
    const int HO = HIN / 2;
    const int PLANE = HO * HO;
    const int NT = PLANE / PT;
    const int CIG = CI / S;
    int blk  = blockIdx.x;
    int tile = blk % NT;
    int co   = (blk / NT) % CO;
    int b    = blk / (NT * CO);
    int tid  = threadIdx.x;
    int pix  = tile*PT + (tid % PT);
    int grp  = tid / PT;

    __shared__ float sw[CI*9];
    __shared__ float sred[TPB];
    for (int i = tid; i < CI*9; i += TPB) sw[i] = w[(size_t)co*CI*9 + i];
    __syncthreads();

    int oy = pix / HO, ox = pix % HO;
    int iy0 = oy*2 - 1, ix0 = ox*2 - 1;
    const float* ib = in + (size_t)(b*CI + grp*CIG)*HIN*HIN;
    const float* wp = sw + grp*CIG*9;
    float acc = 0.f;
    if (iy0 >= 0 && ix0 >= 0) {
        const float* ip = ib + (size_t)iy0*HIN + ix0;
        for (int ci = 0; ci < CIG; ci++) {
            acc += ip[0]      *wp[0] + ip[1]      *wp[1] + ip[2]      *wp[2];
            acc += ip[HIN]    *wp[3] + ip[HIN+1]  *wp[4] + ip[HIN+2]  *wp[5];
            acc += ip[2*HIN]  *wp[6] + ip[2*HIN+1]*wp[7] + ip[2*HIN+2]*wp[8];
            ip += HIN*HIN;
            wp += 9;
        }
    } else {
        for (int ci = 0; ci < CIG; ci++) {
            const float* ip = ib + (size_t)ci*HIN*HIN;
            const float* wq = wp + ci*9;
            #pragma unroll
            for (int ky = 0; ky < 3; ky++) {
                int iy = iy0 + ky;
                if ((unsigned)iy >= (unsigned)HIN) continue;
                #pragma unroll
                for (int kx = 0; kx < 3; kx++) {
                    int ix = ix0 + kx;
                    if ((unsigned)ix >= (unsigned)HIN) continue;
                    acc += ip[iy*HIN + ix] * wq[ky*3 + kx];
                }
            }
        }
    }
    sred[tid] = acc;
    __syncthreads();
    #pragma unroll
    for (int s = S/2; s > 0; s >>= 1) {
        if (grp < s) sred[tid] += sred[tid + s*PT];
        __syncthreads();
    }
    if (grp == 0) {
        float v = sred[tid] + bias[co];
        out[(size_t)(b*CO + co)*PLANE + pix] = v >= 0.f ? v : 0.2f*v;
    }
}

// ---------- instance norm, in place, float4-vectorized (block per (b,c)) -----
__global__ void inorm_k(float* __restrict__ x, const float* __restrict__ g,
                        const float* __restrict__ be, int C, int N) {
    int bc = blockIdx.x;
    int c  = bc % C;
    float4* p = (float4*)(x + (size_t)bc * N);
    int n4 = N >> 2;
    float s = 0.f, s2 = 0.f;
    for (int i = threadIdx.x; i < n4; i += blockDim.x) {
        float4 v = p[i];
        s  += v.x + v.y + v.z + v.w;
        s2 += v.x*v.x + v.y*v.y + v.z*v.z + v.w*v.w;
    }
    __shared__ float sa[256], sb[256];
    sa[threadIdx.x] = s; sb[threadIdx.x] = s2;
    __syncthreads();
    for (int o = 128; o > 0; o >>= 1) {
        if (threadIdx.x < o) { sa[threadIdx.x] += sa[threadIdx.x+o]; sb[threadIdx.x] += sb[threadIdx.x+o]; }
        __syncthreads();
    }
    __shared__ float s_a, s_b;
    if (threadIdx.x == 0) {
        float m   = sa[0] / (float)N;
        float var = sb[0] / (float)N - m*m;
        float inv = rsqrtf(var + 1e-5f);
        float a   = inv * g[c];
        s_a = a;
        s_b = be[c] - m * a;
    }
    __syncthreads();
    float a = s_a, bt = s_b;
    for (int i = threadIdx.x; i < n4; i += blockDim.x) {
        float4 v = p[i];
        v.x = v.x*a + bt; v.y = v.y*a + bt; v.z = v.z*a + bt; v.w = v.w*a + bt;
        p[i] = v;
    }
}

// --- pool 8x8 -> (2,2), FCs (4-way split), softmax+cumsum, abs-kink table ----
__global__ void fc_k(const float* __restrict__ wgen_w, const float* __restrict__ wgen_b,
                     const float* __restrict__ ada_w,  const float* __restrict__ ada_b) {
    int b = blockIdx.x;
    int t = threadIdx.x;
    __shared__ float sx[512];
    __shared__ float part[396];
    __shared__ float slog[96];
    __shared__ float sv[3*V];
    {
        int c  = t >> 2;
        int ij = t & 3;
        int i0 = (ij >> 1) * 4;
        int j0 = (ij & 1) * 4;
        const float* p = g_a5 + (size_t)(b*128 + c) * 64;
        float s = 0.f;
        #pragma unroll
        for (int pp = 0; pp < 4; pp++)
            #pragma unroll
            for (int qq = 0; qq < 4; qq++)
                s += p[(i0+pp)*8 + j0+qq];
        sx[t] = s * (1.f/16.f);
    }
    __syncthreads();
    if (t < 384) {
        int o = t >> 2, j = t & 3;
        float d = 0.f;
        int m0 = j * 128;
        for (int m = m0; m < m0 + 128; m++) d += sx[m] * ada_w[m*96 + o];
        part[t] = d;
    } else if (t < 396) {
        int r = t - 384;
        int n = r >> 2, j = r & 3;
        float d = 0.f;
        int m0 = j * 128;
        for (int m = m0; m < m0 + 128; m++) d += sx[m] * wgen_w[m*3 + n];
        part[384 + r] = d;
    }
    __syncthreads();
    if (t < 96) {
        slog[t] = ada_b[t] + part[4*t] + part[4*t+1] + part[4*t+2] + part[4*t+3];
    } else if (t < 99) {
        int n = t - 96;
        g_wts[b*3 + n] = wgen_b[n] + part[384+4*n] + part[384+4*n+1]
                       + part[384+4*n+2] + part[384+4*n+3];
    }
    __syncthreads();
    if (t < 3) {
        float mx = -1e30f;
        for (int k = 0; k < 32; k++) mx = fmaxf(mx, slog[t*32 + k]);
        float e[32]; float sum = 0.f;
        for (int k = 0; k < 32; k++) { e[k] = expf(slog[t*32 + k] - mx); sum += e[k]; }
        float isum = 1.f / sum;
        sv[t*V] = 0.f;
        float run = 0.f;
        for (int k = 0; k < 32; k++) { run += e[k]*isum; sv[t*V + k + 1] = run; }
    }
    __syncthreads();
    // abs-kink bin table: s(q) = m0 + m1*q + d1*|q - qstar|, exact (<=1 vertex/bin)
    for (int i = t; i < 3*256; i += 512) {
        int c = i >> 8;
        int k = i & 255;
        const float* v = sv + c*V;
        float qlo = (float)k * (1.f/256.f);
        float qhi = (float)(k+1) * (1.f/256.f);
        int pos = 0;
        #pragma unroll
        for (int sft = 16; sft >= 1; sft >>= 1)
            if (v[pos + sft] <= qlo) pos += sft;
        float c1a = 1.f / fmaxf(v[pos+1] - v[pos], 1e-10f);
        float a0  = (float)pos - v[pos] * c1a;
        float m0 = a0, m1 = c1a, d1 = 0.f, qs = 0.f;
        float thr = v[pos+1];
        if (thr < qhi && pos < 31) {
            int   ibx = pos + 1;
            float c1b = 1.f / fmaxf(v[ibx+1] - v[ibx], 1e-10f);
            float b0  = (float)ibx - v[ibx] * c1b;
            m0 = 0.5f*(a0 + b0);
            m1 = 0.5f*(c1a + c1b);
            d1 = 0.5f*(c1b - c1a);
            qs = thr;
        }
        g_tbl[(b*3 + c)*256 + k] = make_float4(m0, m1, d1, qs);
    }
}

// ---- build full-cell 64B LUT entries DIRECTLY from basis (lut+pack merged) --
__global__ void lut8_k(const float* __restrict__ basis_w) {
    int i = blockIdx.x * blockDim.x + threadIdx.x;
    if (i >= BATCH*V3) return;
    int b    = i / V3;
    int flat = i % V3;
    int ir   = flat % V;
    int ig   = (flat / V) % V;
    int ibp  = flat / (V*V);
    int dro  = (ir  < V-1) ? 1    : 0;
    int dgo  = (ig  < V-1) ? V    : 0;
    int dbo  = (ibp < V-1) ? V*V  : 0;
    float w0 = g_wts[b*3+0], w1 = g_wts[b*3+1], w2 = g_wts[b*3+2];
    const float* bw = basis_w;
    #define LVAL(ch, f) (w0*bw[0*3*V3 + (ch)*V3 + (f)] + w1*bw[1*3*V3 + (ch)*V3 + (f)] + w2*bw[2*3*V3 + (ch)*V3 + (f)])
    int l00 = flat,        l01 = flat + dro,        l10 = flat + dgo,        l11 = flat + dgo + dro;
    int h00 = flat + dbo,  h01 = h00 + dro,         h10 = h00 + dgo,         h11 = h00 + dgo + dro;
    __half2 lr01 = __floats2half2_rn(LVAL(0,l00), LVAL(0,l01));
    __half2 lr23 = __floats2half2_rn(LVAL(0,l10), LVAL(0,l11));
    __half2 lg01 = __floats2half2_rn(LVAL(1,l00), LVAL(1,l01));
    __half2 lg23 = __floats2half2_rn(LVAL(1,l10), LVAL(1,l11));
    __half2 lb01 = __floats2half2_rn(LVAL(2,l00), LVAL(2,l01));
    __half2 lb23 = __floats2half2_rn(LVAL(2,l10), LVAL(2,l11));
    __half2 hr01 = __floats2half2_rn(LVAL(0,h00), LVAL(0,h01));
    __half2 hr23 = __floats2half2_rn(LVAL(0,h10), LVAL(0,h11));
    __half2 hg01 = __floats2half2_rn(LVAL(1,h00), LVAL(1,h01));
    __half2 hg23 = __floats2half2_rn(LVAL(1,h10), LVAL(1,h11));
    __half2 hb01 = __floats2half2_rn(LVAL(2,h00), LVAL(2,h01));
    __half2 hb23 = __floats2half2_rn(LVAL(2,h10), LVAL(2,h11));
    #undef LVAL
    uint4* d = g_lut8 + (size_t)i*4;
    d[0] = make_uint4(h2u(lr01), h2u(lr23), h2u(lg01), h2u(lg23));
    d[1] = make_uint4(h2u(lb01), h2u(lb23), h2u(hr01), h2u(hr23));
    d[2] = make_uint4(h2u(hg01), h2u(hg23), h2u(hb01), h2u(hb23));
}

// ---------------- trilinear LUT transform ------------------------------------
__device__ __forceinline__ void lut_lookup(const float4* __restrict__ tbl,
                                           float q, int& idx, float& f) {
    q = __saturatef(q);
    int k = min(255, (int)(q * 256.f));
    float4 e = tbl[k];
    float s = fmaf(e.y, q, e.x) + e.z * fabsf(q - e.w);
    int i = min((int)s, 31);
    idx = i;
    f = __saturatef(s - (float)i);
}

__device__ __forceinline__ float3 apply_px(float r, float g, float bl,
        const float4* __restrict__ tr, const float4* __restrict__ tg,
        const float4* __restrict__ tb, const uint4* __restrict__ lb8) {
    int ir, ig, ib;
    float fr, fg, fb;
    lut_lookup(tr, r,  ir, fr);
    lut_lookup(tg, g,  ig, fg);
    lut_lookup(tb, bl, ib, fb);
    int base = ((ib*V + ig)*V + ir) * 4;
    uint4 e0 = __ldg(lb8 + base);
    uint4 e1 = __ldg(lb8 + base + 1);
    uint4 e2 = __ldg(lb8 + base + 2);
    float w00 = (1.f-fg)*(1.f-fr);
    float w01 = (1.f-fg)*fr;
    float w10 = fg*(1.f-fr);
    float w11 = fg*fr;
    #define H2F(u) __half22float2(*reinterpret_cast<const __half2*>(&(u)))
    float2 lr01 = H2F(e0.x), lr23 = H2F(e0.y), lg01 = H2F(e0.z), lg23 = H2F(e0.w);
    float2 lb01 = H2F(e1.x), lb23 = H2F(e1.y);
    float2 hr01 = H2F(e1.z), hr23 = H2F(e1.w);
    float2 hg01 = H2F(e2.x), hg23 = H2F(e2.y), hb01 = H2F(e2.z), hb23 = H2F(e2.w);
    #undef H2F
    float lox = w00*lr01.x + w01*lr01.y + w10*lr23.x + w11*lr23.y;
    float loy = w00*lg01.x + w01*lg01.y + w10*lg23.x + w11*lg23.y;
    float loz = w00*lb01.x + w01*lb01.y + w10*lb23.x + w11*lb23.y;
    float hix = w00*hr01.x + w01*hr01.y + w10*hr23.x + w11*hr23.y;
    float hiy = w00*hg01.x + w01*hg01.y + w10*hg23.x + w11*hg23.y;
    float hiz = w00*hb01.x + w01*hb01.y + w10*hb23.x + w11*hb23.y;
    float omfb = 1.f - fb;
    return make_float3(omfb*lox + fb*hix, omfb*loy + fb*hiy, omfb*loz + fb*hiz);
}

__global__ __launch_bounds__(256) void trans_k(const float* __restrict__ img,
                                               float* __restrict__ out) {
    __shared__ float4 stbl[3*256];
    const int PPT = 16;                                 // pixels per thread
    const int BPB = (NPIX/PPT) / 256;                   // blocks per batch = 1024
    int b   = blockIdx.x / BPB;
    int blk = blockIdx.x % BPB;

    for (int i = threadIdx.x; i < 3*256; i += 256) stbl[i] = g_tbl[b*3*256 + i];
    __syncthreads();

    int q16 = blk*256 + threadIdx.x;                    // chunk of 16 pixels
    int q   = q16 * 4;                                  // float4 index (4 per chunk)

    const float4* rp = (const float4*)(img + (size_t)(b*3+0)*NPIX);
    const float4* gp = (const float4*)(img + (size_t)(b*3+1)*NPIX);
    const float4* bp = (const float4*)(img + (size_t)(b*3+2)*NPIX);
    const float4* tr = stbl;
    const float4* tg = stbl + 256;
    const float4* tb = stbl + 512;
    const uint4*  lb8 = g_lut8 + (size_t)b*V3*4;

    float4* orp = (float4*)(out + (size_t)(b*3+0)*NPIX);
    float4* ogp = (float4*)(out + (size_t)(b*3+1)*NPIX);
    float4* obp = (float4*)(out + (size_t)(b*3+2)*NPIX);

    #pragma unroll
    for (int h = 0; h < 4; h++) {
        float4 R = rp[q+h], G = gp[q+h], Bl = bp[q+h];
        float3 o0 = apply_px(R.x, G.x, Bl.x, tr, tg, tb, lb8);
        float3 o1 = apply_px(R.y, G.y, Bl.y, tr, tg, tb, lb8);
        float3 o2 = apply_px(R.z, G.z, Bl.z, tr, tg, tb, lb8);
        float3 o3 = apply_px(R.w, G.w, Bl.w, tr, tg, tb, lb8);
        orp[q+h] = make_float4(o0.x, o1.x, o2.x, o3.x);
        ogp[q+h] = make_float4(o0.y, o1.y, o2.y, o3.y);
        obp[q+h] = make_float4(o0.z, o1.z, o2.z, o3.z);
    }
}

// ---------------- launch ------------------------------------------------------
extern "C" void kernel_launch(void* const* d_in, const int* in_sizes, int n_in,
                              void* d_out, int out_size) {
    const float* imgs   = (const float*)d_in[0];
    const float* w1 = (const float*)d_in[1];  const float* b1 = (const float*)d_in[2];
    const float* g1 = (const float*)d_in[3];  const float* be1 = (const float*)d_in[4];
    const float* w2 = (const float*)d_in[5];  const float* b2 = (const float*)d_in[6];
    const float* g2 = (const float*)d_in[7];  const float* be2 = (const float*)d_in[8];
    const float* w3 = (const float*)d_in[9];  const float* b3 = (const float*)d_in[10];
    const float* g3 = (const float*)d_in[11]; const float* be3 = (const float*)d_in[12];
    const float* w4 = (const float*)d_in[13]; const float* b4 = (const float*)d_in[14];
    const float* g4 = (const float*)d_in[15]; const float* be4 = (const float*)d_in[16];
    const float* w5 = (const float*)d_in[17]; const float* b5 = (const float*)d_in[18];
    const float* wgen_w = (const float*)d_in[19]; const float* wgen_b = (const float*)d_in[20];
    const float* basis_w = (const float*)d_in[21];
    const float* ada_w = (const float*)d_in[22]; const float* ada_b = (const float*)d_in[23];
    float* out = (float*)d_out;

    void *p_rs, *p_a1, *p_a2, *p_a3, *p_a4, *p_a5;
    cudaGetSymbolAddress(&p_rs, g_rs);
    cudaGetSymbolAddress(&p_a1, g_a1);
    cudaGetSymbolAddress(&p_a2, g_a2);
    cudaGetSymbolAddress(&p_a3, g_a3);
    cudaGetSymbolAddress(&p_a4, g_a4);
    cudaGetSymbolAddress(&p_a5, g_a5);

    const int T = 256;

    resize_k<<<(BATCH*3*256*256 + T-1)/T, T>>>(imgs);

    conv_k<3,  16, 256, 256><<<BATCH*16*(128*128/256), 256>>>((const float*)p_rs, w1, b1, (float*)p_a1);
    inorm_k<<<BATCH*16,  T>>>((float*)p_a1, g1, be1, 16, 128*128);
    convs_k<16, 32, 128, 256, 2, 512><<<BATCH*32*16, 512>>>((const float*)p_a1, w2, b2, (float*)p_a2);
    inorm_k<<<BATCH*32,  T>>>((float*)p_a2, g2, be2, 32, 64*64);
    convs_k<32, 64, 64, 256, 4, 1024><<<BATCH*64*4, 1024>>>((const float*)p_a2, w3, b3, (float*)p_a3);
    inorm_k<<<BATCH*64,  T>>>((float*)p_a3, g3, be3, 64, 32*32);
    convs_k<64, 128, 32, 256, 2, 512><<<BATCH*128, 512>>>((const float*)p_a3, w4, b4, (float*)p_a4);
    inorm_k<<<BATCH*128, T>>>((float*)p_a4, g4, be4, 128, 16*16);
    convs_k<128,128, 16, 64, 4, 256><<<BATCH*128, 256>>>((const float*)p_a4, w5, b5, (float*)p_a5);

    fc_k<<<BATCH, 512>>>(wgen_w, wgen_b, ada_w, ada_b);
    lut8_k<<<(BATCH*V3 + T-1)/T, T>>>(basis_w);

    trans_k<<<BATCH*((NPIX/16)/256), 256>>>(imgs, out);
}

// round 17
// speedup vs baseline: 1.1166x; 1.1166x over previous
#include <cuda_runtime.h>
#include <cuda_fp16.h>
#include <cstdint>
#include <math.h>

#define V 33
#define V3 (V*V*V)          // 35937
#define BATCH 2
#define HW 2048
#define NPIX (HW*HW)

// ---------------- scratch (static device globals; no allocation) -------------
__device__ float  g_rs[BATCH*3*256*256];
__device__ float  g_a1[BATCH*16*128*128];
__device__ float  g_a2[BATCH*32*64*64];
__device__ float  g_a3[BATCH*64*32*32];
__device__ float  g_a4[BATCH*128*16*16];
__device__ float  g_a5[BATCH*128*8*8];
__device__ float  g_wts[BATCH*3];
// abs-kink bin table: per (b,c,k): {m0, m1, d1, qstar}; s(q)=m0+m1*q+d1*|q-qstar|
__device__ float4 g_tbl[BATCH*3*256];
// full-cell 64B entries: all 8 corners x 3ch (48B payload), 1 L1 line/pixel
__device__ uint4 g_lut8[BATCH*V3*4];

__device__ __forceinline__ unsigned int h2u(__half2 h) {
    return *reinterpret_cast<unsigned int*>(&h);
}

// ---------------- stage 1: bilinear 2048 -> 256 (scale exactly 8) ------------
__global__ void resize_k(const float* __restrict__ img) {
    int i = blockIdx.x * blockDim.x + threadIdx.x;
    if (i >= BATCH*3*256*256) return;
    int ox = i & 255;
    int oy = (i >> 8) & 255;
    int pc = i >> 16;                       // b*3 + c
    const float* p = img + (size_t)pc * NPIX;
    int iy = oy*8 + 3, ix = ox*8 + 3;
    float p00 = p[(size_t)iy*HW + ix];
    float p01 = p[(size_t)iy*HW + ix + 1];
    float p10 = p[(size_t)(iy+1)*HW + ix];
    float p11 = p[(size_t)(iy+1)*HW + ix + 1];
    float r0 = 0.5f*p00 + 0.5f*p10;
    float r1 = 0.5f*p01 + 0.5f*p11;
    g_rs[i] = 0.5f*r0 + 0.5f*r1;
}

// ------- thread-per-output conv, weights in smem (shallow CI) ----------------
template<int CI, int CO, int HIN, int TPB>
__global__ __launch_bounds__(TPB) void conv_k(const float* __restrict__ in,
                       const float* __restrict__ w,
                       const float* __restrict__ bias, float* __restrict__ out) {
    const int HO = HIN / 2;
    const int PLANE = HO * HO;
    const int BPP = PLANE / TPB;
    int blk  = blockIdx.x;
    int pix  = (blk % BPP) * TPB + threadIdx.x;
    int co   = (blk / BPP) % CO;
    int b    = blk / (BPP * CO);

    __shared__ float sw[CI*9];
    for (int i = threadIdx.x; i < CI*9; i += TPB) sw[i] = w[(size_t)co*CI*9 + i];
    __syncthreads();

    int ox = pix % HO;
    int oy = pix / HO;
    float acc = bias[co];
    const float* ib = in + (size_t)b*CI*HIN*HIN;
    int iy0 = oy*2 - 1, ix0 = ox*2 - 1;
    if (iy0 >= 0 && ix0 >= 0) {
        const float* ip = ib + (size_t)iy0*HIN + ix0;
        const float* wp = sw;
        for (int ci = 0; ci < CI; ci++) {
            acc += ip[0]      *wp[0] + ip[1]      *wp[1] + ip[2]      *wp[2];
            acc += ip[HIN]    *wp[3] + ip[HIN+1]  *wp[4] + ip[HIN+2]  *wp[5];
            acc += ip[2*HIN]  *wp[6] + ip[2*HIN+1]*wp[7] + ip[2*HIN+2]*wp[8];
            ip += HIN*HIN;
            wp += 9;
        }
    } else {
        for (int ci = 0; ci < CI; ci++) {
            const float* ip = ib + (size_t)ci*HIN*HIN;
            const float* wp = sw + ci*9;
            #pragma unroll
            for (int ky = 0; ky < 3; ky++) {
                int iy = iy0 + ky;
                if ((unsigned)iy >= (unsigned)HIN) continue;
                #pragma unroll
                for (int kx = 0; kx < 3; kx++) {
                    int ix = ix0 + kx;
                    if ((unsigned)ix >= (unsigned)HIN) continue;
                    acc += ip[iy*HIN + ix] * wp[ky*3 + kx];
                }
            }
        }
    }
    out[(size_t)(b*CO + co)*PLANE + pix] = acc >= 0.f ? acc : 0.2f*acc;
}

// ---- ci-split conv: block = PT pixels x S ci-groups; smem tree-reduce -------
template<int CI, int CO, int HIN, int PT, int S, int TPB>
__global__ __launch_bounds__(TPB) void convs_k(const float* __restrict__ in,
                       const float* __restrict__ w,
                       const float* __restrict__ bias, float* __restrict__ out) {
    const int HO = HIN / 2;
    const int PLANE = HO * HO;
    const int NT = PLANE / PT;
    const int CIG = CI / S;
    int blk  = blockIdx.x;
    int tile = blk % NT;
    int co   = (blk / NT) % CO;
    int b    = blk / (NT * CO);
    int tid  = threadIdx.x;
    int pix  = tile*PT + (tid % PT);
    int grp  = tid / PT;

    __shared__ float sw[CI*9];
    __shared__ float sred[TPB];
    for (int i = tid; i < CI*9; i += TPB) sw[i] = w[(size_t)co*CI*9 + i];
    __syncthreads();

    int oy = pix / HO, ox = pix % HO;
    int iy0 = oy*2 - 1, ix0 = ox*2 - 1;
    const float* ib = in + (size_t)(b*CI + grp*CIG)*HIN*HIN;
    const float* wp = sw + grp*CIG*9;
    float acc = 0.f;
    if (iy0 >= 0 && ix0 >= 0) {
        const float* ip = ib + (size_t)iy0*HIN + ix0;
        for (int ci = 0; ci < CIG; ci++) {
            acc += ip[0]      *wp[0] + ip[1]      *wp[1] + ip[2]      *wp[2];
            acc += ip[HIN]    *wp[3] + ip[HIN+1]  *wp[4] + ip[HIN+2]  *wp[5];
            acc += ip[2*HIN]  *wp[6] + ip[2*HIN+1]*wp[7] + ip[2*HIN+2]*wp[8];
            ip += HIN*HIN;
            wp += 9;
        }
    } else {
        for (int ci = 0; ci < CIG; ci++) {
            const float* ip = ib + (size_t)ci*HIN*HIN;
            const float* wq = wp + ci*9;
            #pragma unroll
            for (int ky = 0; ky < 3; ky++) {
                int iy = iy0 + ky;
                if ((unsigned)iy >= (unsigned)HIN) continue;
                #pragma unroll
                for (int kx = 0; kx < 3; kx++) {
                    int ix = ix0 + kx;
                    if ((unsigned)ix >= (unsigned)HIN) continue;
                    acc += ip[iy*HIN + ix] * wq[ky*3 + kx];
                }
            }
        }
    }
    sred[tid] = acc;
    __syncthreads();
    #pragma unroll
    for (int s = S/2; s > 0; s >>= 1) {
        if (grp < s) sred[tid] += sred[tid + s*PT];
        __syncthreads();
    }
    if (grp == 0) {
        float v = sred[tid] + bias[co];
        out[(size_t)(b*CO + co)*PLANE + pix] = v >= 0.f ? v : 0.2f*v;
    }
}

// ---------- instance norm, in place, float4-vectorized (block per (b,c)) -----
__global__ void inorm_k(float* __restrict__ x, const float* __restrict__ g,
                        const float* __restrict__ be, int C, int N) {
    int bc = blockIdx.x;
    int c  = bc % C;
    float4* p = (float4*)(x + (size_t)bc * N);
    int n4 = N >> 2;
    float s = 0.f, s2 = 0.f;
    for (int i = threadIdx.x; i < n4; i += blockDim.x) {
        float4 v = p[i];
        s  += v.x + v.y + v.z + v.w;
        s2 += v.x*v.x + v.y*v.y + v.z*v.z + v.w*v.w;
    }
    __shared__ float sa[256], sb[256];
    sa[threadIdx.x] = s; sb[threadIdx.x] = s2;
    __syncthreads();
    for (int o = 128; o > 0; o >>= 1) {
        if (threadIdx.x < o) { sa[threadIdx.x] += sa[threadIdx.x+o]; sb[threadIdx.x] += sb[threadIdx.x+o]; }
        __syncthreads();
    }
    __shared__ float s_a, s_b;
    if (threadIdx.x == 0) {
        float m   = sa[0] / (float)N;
        float var = sb[0] / (float)N - m*m;
        float inv = rsqrtf(var + 1e-5f);
        float a   = inv * g[c];
        s_a = a;
        s_b = be[c] - m * a;
    }
    __syncthreads();
    float a = s_a, bt = s_b;
    for (int i = threadIdx.x; i < n4; i += blockDim.x) {
        float4 v = p[i];
        v.x = v.x*a + bt; v.y = v.y*a + bt; v.z = v.z*a + bt; v.w = v.w*a + bt;
        p[i] = v;
    }
}

// --- pool 8x8 -> (2,2), FCs (4-way split), softmax+cumsum, abs-kink table ----
__global__ void fc_k(const float* __restrict__ wgen_w, const float* __restrict__ wgen_b,
                     const float* __restrict__ ada_w,  const float* __restrict__ ada_b) {
    int b = blockIdx.x;
    int t = threadIdx.x;
    __shared__ float sx[512];
    __shared__ float part[396];
    __shared__ float slog[96];
    __shared__ float sv[3*V];
    {
        int c  = t >> 2;
        int ij = t & 3;
        int i0 = (ij >> 1) * 4;
        int j0 = (ij & 1) * 4;
        const float* p = g_a5 + (size_t)(b*128 + c) * 64;
        float s = 0.f;
        #pragma unroll
        for (int pp = 0; pp < 4; pp++)
            #pragma unroll
            for (int qq = 0; qq < 4; qq++)
                s += p[(i0+pp)*8 + j0+qq];
        sx[t] = s * (1.f/16.f);
    }
    __syncthreads();
    if (t < 384) {
        int o = t >> 2, j = t & 3;
        float d = 0.f;
        int m0 = j * 128;
        for (int m = m0; m < m0 + 128; m++) d += sx[m] * ada_w[m*96 + o];
        part[t] = d;
    } else if (t < 396) {
        int r = t - 384;
        int n = r >> 2, j = r & 3;
        float d = 0.f;
        int m0 = j * 128;
        for (int m = m0; m < m0 + 128; m++) d += sx[m] * wgen_w[m*3 + n];
        part[384 + r] = d;
    }
    __syncthreads();
    if (t < 96) {
        slog[t] = ada_b[t] + part[4*t] + part[4*t+1] + part[4*t+2] + part[4*t+3];
    } else if (t < 99) {
        int n = t - 96;
        g_wts[b*3 + n] = wgen_b[n] + part[384+4*n] + part[384+4*n+1]
                       + part[384+4*n+2] + part[384+4*n+3];
    }
    __syncthreads();
    if (t < 3) {
        float mx = -1e30f;
        for (int k = 0; k < 32; k++) mx = fmaxf(mx, slog[t*32 + k]);
        float e[32]; float sum = 0.f;
        for (int k = 0; k < 32; k++) { e[k] = expf(slog[t*32 + k] - mx); sum += e[k]; }
        float isum = 1.f / sum;
        sv[t*V] = 0.f;
        float run = 0.f;
        for (int k = 0; k < 32; k++) { run += e[k]*isum; sv[t*V + k + 1] = run; }
    }
    __syncthreads();
    // abs-kink bin table: s(q) = m0 + m1*q + d1*|q - qstar|, exact (<=1 vertex/bin)
    for (int i = t; i < 3*256; i += 512) {
        int c = i >> 8;
        int k = i & 255;
        const float* v = sv + c*V;
        float qlo = (float)k * (1.f/256.f);
        float qhi = (float)(k+1) * (1.f/256.f);
        int pos = 0;
        #pragma unroll
        for (int sft = 16; sft >= 1; sft >>= 1)
            if (v[pos + sft] <= qlo) pos += sft;
        float c1a = 1.f / fmaxf(v[pos+1] - v[pos], 1e-10f);
        float a0  = (float)pos - v[pos] * c1a;
        float m0 = a0, m1 = c1a, d1 = 0.f, qs = 0.f;
        float thr = v[pos+1];
        if (thr < qhi && pos < 31) {
            int   ibx = pos + 1;
            float c1b = 1.f / fmaxf(v[ibx+1] - v[ibx], 1e-10f);
            float b0  = (float)ibx - v[ibx] * c1b;
            m0 = 0.5f*(a0 + b0);
            m1 = 0.5f*(c1a + c1b);
            d1 = 0.5f*(c1b - c1a);
            qs = thr;
        }
        g_tbl[(b*3 + c)*256 + k] = make_float4(m0, m1, d1, qs);
    }
}

// ---- build full-cell 64B LUT entries DIRECTLY from basis (lut+pack merged) --
__global__ void lut8_k(const float* __restrict__ basis_w) {
    int i = blockIdx.x * blockDim.x + threadIdx.x;
    if (i >= BATCH*V3) return;
    int b    = i / V3;
    int flat = i % V3;
    int ir   = flat % V;
    int ig   = (flat / V) % V;
    int ibp  = flat / (V*V);
    int dro  = (ir  < V-1) ? 1    : 0;
    int dgo  = (ig  < V-1) ? V    : 0;
    int dbo  = (ibp < V-1) ? V*V  : 0;
    float w0 = g_wts[b*3+0], w1 = g_wts[b*3+1], w2 = g_wts[b*3+2];
    const float* bw = basis_w;
    #define LVAL(ch, f) (w0*bw[0*3*V3 + (ch)*V3 + (f)] + w1*bw[1*3*V3 + (ch)*V3 + (f)] + w2*bw[2*3*V3 + (ch)*V3 + (f)])
    int l00 = flat,        l01 = flat + dro,        l10 = flat + dgo,        l11 = flat + dgo + dro;
    int h00 = flat + dbo,  h01 = h00 + dro,         h10 = h00 + dgo,         h11 = h00 + dgo + dro;
    __half2 lr01 = __floats2half2_rn(LVAL(0,l00), LVAL(0,l01));
    __half2 lr23 = __floats2half2_rn(LVAL(0,l10), LVAL(0,l11));
    __half2 lg01 = __floats2half2_rn(LVAL(1,l00), LVAL(1,l01));
    __half2 lg23 = __floats2half2_rn(LVAL(1,l10), LVAL(1,l11));
    __half2 lb01 = __floats2half2_rn(LVAL(2,l00), LVAL(2,l01));
    __half2 lb23 = __floats2half2_rn(LVAL(2,l10), LVAL(2,l11));
    __half2 hr01 = __floats2half2_rn(LVAL(0,h00), LVAL(0,h01));
    __half2 hr23 = __floats2half2_rn(LVAL(0,h10), LVAL(0,h11));
    __half2 hg01 = __floats2half2_rn(LVAL(1,h00), LVAL(1,h01));
    __half2 hg23 = __floats2half2_rn(LVAL(1,h10), LVAL(1,h11));
    __half2 hb01 = __floats2half2_rn(LVAL(2,h00), LVAL(2,h01));
    __half2 hb23 = __floats2half2_rn(LVAL(2,h10), LVAL(2,h11));
    #undef LVAL
    uint4* d = g_lut8 + (size_t)i*4;
    d[0] = make_uint4(h2u(lr01), h2u(lr23), h2u(lg01), h2u(lg23));
    d[1] = make_uint4(h2u(lb01), h2u(lb23), h2u(hr01), h2u(hr23));
    d[2] = make_uint4(h2u(hg01), h2u(hg23), h2u(hb01), h2u(hb23));
}

// ---------------- trilinear LUT transform (proven PPT=8 form) -----------------
__device__ __forceinline__ void lut_lookup(const float4* __restrict__ tbl,
                                           float q, int& idx, float& f) {
    q = __saturatef(q);
    int k = min(255, (int)(q * 256.f));
    float4 e = tbl[k];
    float s = fmaf(e.y, q, e.x) + e.z * fabsf(q - e.w);
    int i = min((int)s, 31);
    idx = i;
    f = __saturatef(s - (float)i);
}

__device__ __forceinline__ float3 apply_px(float r, float g, float bl,
        const float4* __restrict__ tr, const float4* __restrict__ tg,
        const float4* __restrict__ tb, const uint4* __restrict__ lb8) {
    int ir, ig, ib;
    float fr, fg, fb;
    lut_lookup(tr, r,  ir, fr);
    lut_lookup(tg, g,  ig, fg);
    lut_lookup(tb, bl, ib, fb);
    int base = ((ib*V + ig)*V + ir) * 4;
    uint4 e0 = __ldg(lb8 + base);
    uint4 e1 = __ldg(lb8 + base + 1);
    uint4 e2 = __ldg(lb8 + base + 2);
    float w00 = (1.f-fg)*(1.f-fr);
    float w01 = (1.f-fg)*fr;
    float w10 = fg*(1.f-fr);
    float w11 = fg*fr;
    #define H2F(u) __half22float2(*reinterpret_cast<const __half2*>(&(u)))
    float2 lr01 = H2F(e0.x), lr23 = H2F(e0.y), lg01 = H2F(e0.z), lg23 = H2F(e0.w);
    float2 lb01 = H2F(e1.x), lb23 = H2F(e1.y);
    float2 hr01 = H2F(e1.z), hr23 = H2F(e1.w);
    float2 hg01 = H2F(e2.x), hg23 = H2F(e2.y), hb01 = H2F(e2.z), hb23 = H2F(e2.w);
    #undef H2F
    float lox = w00*lr01.x + w01*lr01.y + w10*lr23.x + w11*lr23.y;
    float loy = w00*lg01.x + w01*lg01.y + w10*lg23.x + w11*lg23.y;
    float loz = w00*lb01.x + w01*lb01.y + w10*lb23.x + w11*lb23.y;
    float hix = w00*hr01.x + w01*hr01.y + w10*hr23.x + w11*hr23.y;
    float hiy = w00*hg01.x + w01*hg01.y + w10*hg23.x + w11*hg23.y;
    float hiz = w00*hb01.x + w01*hb01.y + w10*hb23.x + w11*hb23.y;
    float omfb = 1.f - fb;
    return make_float3(omfb*lox + fb*hix, omfb*loy + fb*hiy, omfb*loz + fb*hiz);
}

__global__ __launch_bounds__(256) void trans_k(const float* __restrict__ img,
                                               float* __restrict__ out) {
    __shared__ float4 stbl[3*256];
    const int PPT = 8;
    const int BPB = (NPIX/PPT) / 256;                   // 2048 blocks per batch
    int b   = blockIdx.x / BPB;
    int blk = blockIdx.x % BPB;

    for (int i = threadIdx.x; i < 3*256; i += 256) stbl[i] = g_tbl[b*3*256 + i];
    __syncthreads();

    int q8 = blk*256 + threadIdx.x;
    int q  = q8 * 2;

    const float4* rp = (const float4*)(img + (size_t)(b*3+0)*NPIX);
    const float4* gp = (const float4*)(img + (size_t)(b*3+1)*NPIX);
    const float4* bp = (const float4*)(img + (size_t)(b*3+2)*NPIX);
    const float4* tr = stbl;
    const float4* tg = stbl + 256;
    const float4* tb = stbl + 512;
    const uint4*  lb8 = g_lut8 + (size_t)b*V3*4;

    float4* orp = (float4*)(out + (size_t)(b*3+0)*NPIX);
    float4* ogp = (float4*)(out + (size_t)(b*3+1)*NPIX);
    float4* obp = (float4*)(out + (size_t)(b*3+2)*NPIX);

    #pragma unroll
    for (int h = 0; h < 2; h++) {
        float4 R = rp[q+h], G = gp[q+h], Bl = bp[q+h];
        float3 o0 = apply_px(R.x, G.x, Bl.x, tr, tg, tb, lb8);
        float3 o1 = apply_px(R.y, G.y, Bl.y, tr, tg, tb, lb8);
        float3 o2 = apply_px(R.z, G.z, Bl.z, tr, tg, tb, lb8);
        float3 o3 = apply_px(R.w, G.w, Bl.w, tr, tg, tb, lb8);
        orp[q+h] = make_float4(o0.x, o1.x, o2.x, o3.x);
        ogp[q+h] = make_float4(o0.y, o1.y, o2.y, o3.y);
        obp[q+h] = make_float4(o0.z, o1.z, o2.z, o3.z);
    }
}

// ---------------- launch ------------------------------------------------------
extern "C" void kernel_launch(void* const* d_in, const int* in_sizes, int n_in,
                              void* d_out, int out_size) {
    const float* imgs   = (const float*)d_in[0];
    const float* w1 = (const float*)d_in[1];  const float* b1 = (const float*)d_in[2];
    const float* g1 = (const float*)d_in[3];  const float* be1 = (const float*)d_in[4];
    const float* w2 = (const float*)d_in[5];  const float* b2 = (const float*)d_in[6];
    const float* g2 = (const float*)d_in[7];  const float* be2 = (const float*)d_in[8];
    const float* w3 = (const float*)d_in[9];  const float* b3 = (const float*)d_in[10];
    const float* g3 = (const float*)d_in[11]; const float* be3 = (const float*)d_in[12];
    const float* w4 = (const float*)d_in[13]; const float* b4 = (const float*)d_in[14];
    const float* g4 = (const float*)d_in[15]; const float* be4 = (const float*)d_in[16];
    const float* w5 = (const float*)d_in[17]; const float* b5 = (const float*)d_in[18];
    const float* wgen_w = (const float*)d_in[19]; const float* wgen_b = (const float*)d_in[20];
    const float* basis_w = (const float*)d_in[21];
    const float* ada_w = (const float*)d_in[22]; const float* ada_b = (const float*)d_in[23];
    float* out = (float*)d_out;

    void *p_rs, *p_a1, *p_a2, *p_a3, *p_a4, *p_a5;
    cudaGetSymbolAddress(&p_rs, g_rs);
    cudaGetSymbolAddress(&p_a1, g_a1);
    cudaGetSymbolAddress(&p_a2, g_a2);
    cudaGetSymbolAddress(&p_a3, g_a3);
    cudaGetSymbolAddress(&p_a4, g_a4);
    cudaGetSymbolAddress(&p_a5, g_a5);

    const int T = 256;

    resize_k<<<(BATCH*3*256*256 + T-1)/T, T>>>(imgs);

    conv_k<3,  16, 256, 256><<<BATCH*16*(128*128/256), 256>>>((const float*)p_rs, w1, b1, (float*)p_a1);
    inorm_k<<<BATCH*16,  T>>>((float*)p_a1, g1, be1, 16, 128*128);
    convs_k<16, 32, 128, 256, 2, 512><<<BATCH*32*16, 512>>>((const float*)p_a1, w2, b2, (float*)p_a2);
    inorm_k<<<BATCH*32,  T>>>((float*)p_a2, g2, be2, 32, 64*64);
    convs_k<32, 64, 64, 256, 4, 1024><<<BATCH*64*4, 1024>>>((const float*)p_a2, w3, b3, (float*)p_a3);
    inorm_k<<<BATCH*64,  T>>>((float*)p_a3, g3, be3, 64, 32*32);
    convs_k<64, 128, 32, 256, 2, 512><<<BATCH*128, 512>>>((const float*)p_a3, w4, b4, (float*)p_a4);
    inorm_k<<<BATCH*128, T>>>((float*)p_a4, g4, be4, 128, 16*16);
    convs_k<128,128, 16, 64, 4, 256><<<BATCH*128, 256>>>((const float*)p_a4, w5, b5, (float*)p_a5);

    fc_k<<<BATCH, 512>>>(wgen_w, wgen_b, ada_w, ada_b);
    lut8_k<<<(BATCH*V3 + T-1)/T, T>>>(basis_w);

    trans_k<<<BATCH*((NPIX/8)/256), 256>>>(imgs, out);
}